// round 3
// baseline (speedup 1.0000x reference)
#include <cuda_runtime.h>

#define NWIN  64
#define NHEAD 12
#define LWIN  343
#define DIMM  384
#define HEADD 32
#define TBL   2197
#define MROWS (NWIN * LWIN)            // 21952
#define QK_SCALE 0.1767766952966369f   // 32^-0.5
#define KPAD  36
#define MWPR  12                       // mask words per row (343 bits -> 11, pad 12)

typedef unsigned long long u64;

__device__ __align__(16) float g_q [NWIN * NHEAD * LWIN * HEADD];
__device__ __align__(16) float g_k [NWIN * NHEAD * LWIN * HEADD];
__device__ __align__(16) float g_v [NWIN * NHEAD * LWIN * HEADD];
__device__ __align__(16) float g_ao[MROWS * DIMM];
__device__ int g_mask_mode;            // 0=u8, 1=int32, 2=float32
__device__ unsigned g_maskbits[NWIN * LWIN * MWPR];

union F4U { float4 f; u64 u[2]; };

__device__ __forceinline__ u64 pack2(float a, float b) {
    u64 r; asm("mov.b64 %0,{%1,%2};" : "=l"(r) : "f"(a), "f"(b)); return r;
}
__device__ __forceinline__ float2 unpk2(u64 v) {
    float2 r; asm("mov.b64 {%0,%1},%2;" : "=f"(r.x), "=f"(r.y) : "l"(v)); return r;
}
__device__ __forceinline__ void fma2(u64& d, u64 a, u64 b) {
    asm("fma.rn.f32x2 %0,%1,%2,%0;" : "+l"(d) : "l"(a), "l"(b));
}

// ---------------------------------------------------------------------------
// K0a: detect mask dtype from the first 256 words (1024 bytes).
// ---------------------------------------------------------------------------
__global__ void detect_mask_kernel(const unsigned int* __restrict__ m)
{
    if (threadIdx.x == 0) {
        bool sawF32 = false, sawHigh = false;
        for (int i = 0; i < 256; i++) {
            unsigned w = m[i];
            if (w == 0x3F800000u) sawF32 = true;
            else if (w != 0u && w != 1u) sawHigh = true;
        }
        int mode = 1;                 // default int32
        if (sawHigh) mode = 0;        // packed bytes (bool/u8)
        else if (sawF32) mode = 2;    // float32
        g_mask_mode = mode;
    }
}

// ---------------------------------------------------------------------------
// K0b: bit-pack mask. One thread per output word.
// ---------------------------------------------------------------------------
__global__ __launch_bounds__(256)
void convert_mask_kernel(const void* __restrict__ mraw)
{
    int idx = blockIdx.x * blockDim.x + threadIdx.x;
    if (idx >= NWIN * LWIN * MWPR) return;
    int wi  = idx % MWPR;
    int row = idx / MWPR;                 // win*343 + i
    size_t base = (size_t)(row / LWIN) * LWIN * LWIN + (size_t)(row % LWIN) * LWIN;
    const int mode = g_mask_mode;
    unsigned bits = 0;
    for (int b = 0; b < 32; b++) {
        int j = wi * 32 + b;
        bool mb;
        if (j >= LWIN)          mb = true;
        else if (mode == 0)     mb = ((const unsigned char*)mraw)[base + j] != 0;
        else if (mode == 1)     mb = ((const int*)mraw)[base + j] != 0;
        else                    mb = ((const float*)mraw)[base + j] != 0.0f;
        bits |= (mb ? 1u : 0u) << b;
    }
    g_maskbits[idx] = bits;
}

// ---------------------------------------------------------------------------
// 64x128 output tile GEMM mainloop, K=384, 128 threads, f32x2 accumulators.
// ---------------------------------------------------------------------------
__device__ __forceinline__ void gemm_tile(const float* __restrict__ A,
                                          const float* __restrict__ B,
                                          int Nlen, int m0, int n0,
                                          u64 acc[8][4])
{
    __shared__ float As[16 * 64];
    __shared__ float Bs[16 * 128];

    const int tid = threadIdx.x;
    const int tx = tid & 15, ty = tid >> 4;

#pragma unroll
    for (int i = 0; i < 8; i++)
#pragma unroll
        for (int p = 0; p < 4; p++) acc[i][p] = 0ULL;

    for (int k0 = 0; k0 < DIMM; k0 += 16) {
#pragma unroll
        for (int u = 0; u < 2; u++) {
            int idx = tid + u * 128;
            int row = idx >> 2, c4 = idx & 3;
            float4 av = *(const float4*)(A + (size_t)(m0 + row) * DIMM + k0 + c4 * 4);
            As[(c4 * 4 + 0) * 64 + row] = av.x;
            As[(c4 * 4 + 1) * 64 + row] = av.y;
            As[(c4 * 4 + 2) * 64 + row] = av.z;
            As[(c4 * 4 + 3) * 64 + row] = av.w;
        }
#pragma unroll
        for (int u = 0; u < 4; u++) {
            int idx = tid + u * 128;
            int kr = idx >> 5, c4 = idx & 31;
            *(float4*)(Bs + kr * 128 + c4 * 4) =
                *(const float4*)(B + (size_t)(k0 + kr) * Nlen + n0 + c4 * 4);
        }
        __syncthreads();
#pragma unroll
        for (int k = 0; k < 16; k++) {
            float4 aLo = *(const float4*)(As + k * 64 + ty * 4);
            float4 aHi = *(const float4*)(As + k * 64 + 32 + ty * 4);
            F4U bLo, bHi;
            bLo.f = *(const float4*)(Bs + k * 128 + tx * 4);
            bHi.f = *(const float4*)(Bs + k * 128 + 64 + tx * 4);
            u64 b0 = bLo.u[0], b1 = bLo.u[1], b2 = bHi.u[0], b3 = bHi.u[1];
            float a[8] = {aLo.x, aLo.y, aLo.z, aLo.w, aHi.x, aHi.y, aHi.z, aHi.w};
#pragma unroll
            for (int i = 0; i < 8; i++) {
                u64 a2 = pack2(a[i], a[i]);
                fma2(acc[i][0], a2, b0);
                fma2(acc[i][1], a2, b1);
                fma2(acc[i][2], a2, b2);
                fma2(acc[i][3], a2, b3);
            }
        }
        __syncthreads();
    }
}

// ---------------------------------------------------------------------------
// K1: QKV projection + scatter. grid(9, 343), 128 threads.
// ---------------------------------------------------------------------------
__global__ __launch_bounds__(128)
void qkv_gemm_kernel(const float* __restrict__ x, const float* __restrict__ w)
{
    u64 acc[8][4];
    const int m0 = blockIdx.y * 64, n0 = blockIdx.x * 128;
    gemm_tile(x, w, 3 * DIMM, m0, n0, acc);

    const int tx = threadIdx.x & 15, ty = threadIdx.x >> 4;
    const int three = n0 / DIMM;                  // 0=q, 1=k, 2=v
    float* dst = (three == 0) ? g_q : (three == 1 ? g_k : g_v);
    const float sc = (three == 0) ? QK_SCALE : 1.0f;
    const int nb = n0 - three * DIMM;

#pragma unroll
    for (int i = 0; i < 8; i++) {
        int r = m0 + ((i < 4) ? (ty * 4 + i) : (32 + ty * 4 + i - 4));
        int n = r / LWIN, l = r - n * LWIN;
#pragma unroll
        for (int p = 0; p < 4; p++) {
            float2 v = unpk2(acc[i][p]);
            int c0 = nb + ((p < 2) ? (tx * 4 + 2 * p) : (64 + tx * 4 + 2 * (p - 2)));
            int h  = c0 >> 5, ch = c0 & 31;
            dst[(size_t)((n * NHEAD + h) * LWIN + l) * HEADD + ch] = v.x * sc;
            int c1 = c0 + 1; h = c1 >> 5; ch = c1 & 31;
            dst[(size_t)((n * NHEAD + h) * LWIN + l) * HEADD + ch] = v.y * sc;
        }
    }
}

// ---------------------------------------------------------------------------
// K2: fused attention. grid(12, 64) = (head, window), 512 threads.
// ---------------------------------------------------------------------------
#define ATTN_SMEM_FLOATS (LWIN * KPAD * 2 + 16 * 1408 + 16 * 128 + 2208)
#define ATTN_SMEM_BYTES  (ATTN_SMEM_FLOATS * 4)

__global__ __launch_bounds__(512, 1)
void attn_kernel(const int* __restrict__ rel_idx,
                 const float* __restrict__ table)
{
    extern __shared__ float smem[];
    float* Ks       = smem;                       // [343][36]
    float* Vs       = smem + LWIN * KPAD;         // [343][36]
    float* srow_all = Vs + LWIN * KPAD;           // 16 x [352][4]
    float* qbuf_all = srow_all + 16 * 1408;       // 16 x [4][32]
    float* tb       = qbuf_all + 16 * 128;        // table[:, h], 2197 (+pad)

    const int h    = blockIdx.x;
    const int win  = blockIdx.y;
    const int tid  = threadIdx.x;
    const int lane = tid & 31;
    const int warp = tid >> 5;
    const size_t base = (size_t)(win * NHEAD + h) * LWIN * HEADD;

    for (int idx = tid; idx < LWIN * HEADD; idx += 512) {
        int row = idx >> 5, c = idx & 31;
        Ks[row * KPAD + c] = g_k[base + idx];
        Vs[row * KPAD + c] = g_v[base + idx];
    }
    for (int idx = tid; idx < TBL; idx += 512)
        tb[idx] = __ldg(table + (size_t)idx * NHEAD + h);
    __syncthreads();

    float* sw = srow_all + warp * 1408;
    float* qb = qbuf_all + warp * 128;
    const unsigned* mbits = g_maskbits + (size_t)win * LWIN * MWPR;

    for (int rg = warp; rg < 86; rg += 16) {      // ceil(343/4) row groups
        const int r0 = rg * 4;
#pragma unroll
        for (int r = 0; r < 4; r++) {
            int ri = min(r0 + r, LWIN - 1);
            qb[r * 32 + lane] = g_q[base + (size_t)ri * HEADD + lane];
        }
        __syncwarp();

        // stage 1: S = Q K^T + bias, masked
        float lmax[4] = {-1e30f, -1e30f, -1e30f, -1e30f};
        for (int jt = 0; jt < LWIN; jt += 32) {
            int j  = jt + lane;
            int jj = min(j, LWIN - 1);
            u64 a0 = 0, a1 = 0, a2 = 0, a3 = 0;
            const F4U* kp = (const F4U*)(Ks + jj * KPAD);
#pragma unroll
            for (int c4 = 0; c4 < 8; c4++) {
                F4U k4 = kp[c4];
                F4U q;
                q.f = *(const float4*)(qb +  0 + c4 * 4);
                fma2(a0, q.u[0], k4.u[0]); fma2(a0, q.u[1], k4.u[1]);
                q.f = *(const float4*)(qb + 32 + c4 * 4);
                fma2(a1, q.u[0], k4.u[0]); fma2(a1, q.u[1], k4.u[1]);
                q.f = *(const float4*)(qb + 64 + c4 * 4);
                fma2(a2, q.u[0], k4.u[0]); fma2(a2, q.u[1], k4.u[1]);
                q.f = *(const float4*)(qb + 96 + c4 * 4);
                fma2(a3, q.u[0], k4.u[0]); fma2(a3, q.u[1], k4.u[1]);
            }
            float s[4];
            { float2 t = unpk2(a0); s[0] = t.x + t.y; }
            { float2 t = unpk2(a1); s[1] = t.x + t.y; }
            { float2 t = unpk2(a2); s[2] = t.x + t.y; }
            { float2 t = unpk2(a3); s[3] = t.x + t.y; }
#pragma unroll
            for (int r = 0; r < 4; r++) {
                int ri = min(r0 + r, LWIN - 1);
                int bi = __ldg(rel_idx + (size_t)ri * LWIN + jj);
                float sv = s[r] + tb[bi];
                unsigned w = mbits[ri * MWPR + (jt >> 5)];
                if ((w >> lane) & 1u) sv = -1e30f;   // covers j >= LWIN too (pad bits = 1)
                s[r] = sv;
                lmax[r] = fmaxf(lmax[r], sv);
            }
            *(float4*)(sw + j * 4) = make_float4(s[0], s[1], s[2], s[3]);
        }
        __syncwarp();

        // stage 2: two-pass softmax
        float m[4];
#pragma unroll
        for (int r = 0; r < 4; r++) {
            float v = lmax[r];
#pragma unroll
            for (int off = 16; off > 0; off >>= 1)
                v = fmaxf(v, __shfl_xor_sync(0xffffffffu, v, off));
            m[r] = v;
        }
        float lsum[4] = {0.f, 0.f, 0.f, 0.f};
        for (int jt = 0; jt < LWIN; jt += 32) {
            int j = jt + lane;
            float4 p = *(float4*)(sw + j * 4);
            p.x = __expf(p.x - m[0]); lsum[0] += p.x;
            p.y = __expf(p.y - m[1]); lsum[1] += p.y;
            p.z = __expf(p.z - m[2]); lsum[2] += p.z;
            p.w = __expf(p.w - m[3]); lsum[3] += p.w;
            *(float4*)(sw + j * 4) = p;
        }
        __syncwarp();
        float inv[4];
#pragma unroll
        for (int r = 0; r < 4; r++) {
            float v = lsum[r];
#pragma unroll
            for (int off = 16; off > 0; off >>= 1)
                v += __shfl_xor_sync(0xffffffffu, v, off);
            inv[r] = 1.0f / v;
        }

        // stage 3: O = P V (lane = output channel)
        u64 oA0 = 0, oA1 = 0, oB0 = 0, oB1 = 0;
        const float* vp = Vs + lane;
        for (int j = 0; j < LWIN - 1; j += 2) {
            float v0 = vp[j * KPAD];
            float v1 = vp[(j + 1) * KPAD];
            F4U p0; p0.f = *(const float4*)(sw + j * 4);
            F4U p1; p1.f = *(const float4*)(sw + (j + 1) * 4);
            u64 w0 = pack2(v0, v0), w1 = pack2(v1, v1);
            fma2(oA0, p0.u[0], w0); fma2(oA1, p0.u[1], w0);
            fma2(oB0, p1.u[0], w1); fma2(oB1, p1.u[1], w1);
        }
        {   // j = 342 tail
            float v = vp[(LWIN - 1) * KPAD];
            F4U p; p.f = *(const float4*)(sw + (LWIN - 1) * 4);
            u64 w = pack2(v, v);
            fma2(oA0, p.u[0], w); fma2(oA1, p.u[1], w);
        }
        float2 eA0 = unpk2(oA0), eB0 = unpk2(oB0);
        float2 eA1 = unpk2(oA1), eB1 = unpk2(oB1);
        float o[4];
        o[0] = (eA0.x + eB0.x) * inv[0];
        o[1] = (eA0.y + eB0.y) * inv[1];
        o[2] = (eA1.x + eB1.x) * inv[2];
        o[3] = (eA1.y + eB1.y) * inv[3];
#pragma unroll
        for (int r = 0; r < 4; r++) {
            int ri = min(r0 + r, LWIN - 1);
            g_ao[(size_t)(win * LWIN + ri) * DIMM + h * HEADD + lane] = o[r];
        }
        __syncwarp();
    }
}

// ---------------------------------------------------------------------------
// K3: out = g_ao @ proj_w + proj_b. grid(3, 343), 128 threads.
// ---------------------------------------------------------------------------
__global__ __launch_bounds__(128)
void proj_gemm_kernel(const float* __restrict__ w, const float* __restrict__ b,
                      float* __restrict__ out)
{
    u64 acc[8][4];
    const int m0 = blockIdx.y * 64, n0 = blockIdx.x * 128;
    gemm_tile(g_ao, w, DIMM, m0, n0, acc);

    const int tx = threadIdx.x & 15, ty = threadIdx.x >> 4;
#pragma unroll
    for (int i = 0; i < 8; i++) {
        int r = m0 + ((i < 4) ? (ty * 4 + i) : (32 + ty * 4 + i - 4));
#pragma unroll
        for (int p = 0; p < 4; p++) {
            float2 v = unpk2(acc[i][p]);
            int c0 = n0 + ((p < 2) ? (tx * 4 + 2 * p) : (64 + tx * 4 + 2 * (p - 2)));
            out[(size_t)r * DIMM + c0]     = v.x + b[c0];
            out[(size_t)r * DIMM + c0 + 1] = v.y + b[c0 + 1];
        }
    }
}

extern "C" void kernel_launch(void* const* d_in, const int* in_sizes, int n_in,
                              void* d_out, int out_size)
{
    const float* x       = (const float*)d_in[0];
    const float* qkv_w   = (const float*)d_in[1];
    const float* table   = (const float*)d_in[2];
    const float* proj_w  = (const float*)d_in[3];
    const float* proj_b  = (const float*)d_in[4];
    const void*  mask    = d_in[5];
    const int*   rel_idx = (const int*)d_in[6];
    float*       out     = (float*)d_out;

    detect_mask_kernel<<<1, 32>>>((const unsigned int*)mask);
    convert_mask_kernel<<<(NWIN * LWIN * MWPR + 255) / 256, 256>>>(mask);

    qkv_gemm_kernel<<<dim3(9, 343), 128>>>(x, qkv_w);

    cudaFuncSetAttribute(attn_kernel, cudaFuncAttributeMaxDynamicSharedMemorySize,
                         ATTN_SMEM_BYTES);
    attn_kernel<<<dim3(NHEAD, NWIN), 512, ATTN_SMEM_BYTES>>>(rel_idx, table);

    proj_gemm_kernel<<<dim3(3, 343), 128>>>(proj_w, proj_b, out);
}

// round 4
// speedup vs baseline: 1.1670x; 1.1670x over previous
#include <cuda_runtime.h>

#define NWIN  64
#define NHEAD 12
#define LWIN  343
#define DIMM  384
#define HEADD 32
#define TBL   2197
#define MROWS (NWIN * LWIN)            // 21952
#define QK_SCALE 0.1767766952966369f   // 32^-0.5
#define MWPR  12                       // mask words per row
#define BJ    352                      // padded j for bias table
#define BI    344                      // padded i stride for bias table
#define NCHUNK 11                      // 11 * 32 = 352 >= 343

typedef unsigned long long u64;

__device__ __align__(16) float g_q [NWIN * NHEAD * LWIN * HEADD];
__device__ __align__(16) float g_k [NWIN * NHEAD * LWIN * HEADD];
__device__ __align__(16) float g_v [NWIN * NHEAD * LWIN * HEADD];
__device__ __align__(16) float g_ao[MROWS * DIMM];
__device__ __align__(16) float g_bias[NHEAD * BJ * BI];   // biasT[h][j][i]
__device__ int g_mask_mode;            // 0=u8, 1=int32, 2=float32
__device__ unsigned g_maskbits[NWIN * LWIN * MWPR];

union F4U { float4 f; u64 u[2]; };

__device__ __forceinline__ u64 pack2(float a, float b) {
    u64 r; asm("mov.b64 %0,{%1,%2};" : "=l"(r) : "f"(a), "f"(b)); return r;
}
__device__ __forceinline__ float2 unpk2(u64 v) {
    float2 r; asm("mov.b64 {%0,%1},%2;" : "=f"(r.x), "=f"(r.y) : "l"(v)); return r;
}
__device__ __forceinline__ void fma2(u64& d, u64 a, u64 b) {
    asm("fma.rn.f32x2 %0,%1,%2,%0;" : "+l"(d) : "l"(a), "l"(b));
}
__device__ __forceinline__ void mul2(u64& d, u64 s) {
    asm("mul.rn.f32x2 %0,%0,%1;" : "+l"(d) : "l"(s));
}

// ---------------------------------------------------------------------------
// K0a: detect mask dtype from the first 256 words.
// ---------------------------------------------------------------------------
__global__ void detect_mask_kernel(const unsigned int* __restrict__ m)
{
    if (threadIdx.x == 0) {
        bool sawF32 = false, sawHigh = false;
        for (int i = 0; i < 256; i++) {
            unsigned w = m[i];
            if (w == 0x3F800000u) sawF32 = true;
            else if (w != 0u && w != 1u) sawHigh = true;
        }
        int mode = 1;
        if (sawHigh) mode = 0;
        else if (sawF32) mode = 2;
        g_mask_mode = mode;
    }
}

// ---------------------------------------------------------------------------
// K0b: bit-pack mask. One thread per output word. Pad bits (j>=LWIN) = 1.
// ---------------------------------------------------------------------------
__global__ __launch_bounds__(256)
void convert_mask_kernel(const void* __restrict__ mraw)
{
    int idx = blockIdx.x * blockDim.x + threadIdx.x;
    if (idx >= NWIN * LWIN * MWPR) return;
    int wi  = idx % MWPR;
    int row = idx / MWPR;
    size_t base = (size_t)(row / LWIN) * LWIN * LWIN + (size_t)(row % LWIN) * LWIN;
    const int mode = g_mask_mode;
    unsigned bits = 0;
    for (int b = 0; b < 32; b++) {
        int j = wi * 32 + b;
        bool mb;
        if (j >= LWIN)          mb = true;
        else if (mode == 0)     mb = ((const unsigned char*)mraw)[base + j] != 0;
        else if (mode == 1)     mb = ((const int*)mraw)[base + j] != 0;
        else                    mb = ((const float*)mraw)[base + j] != 0.0f;
        bits |= (mb ? 1u : 0u) << b;
    }
    g_maskbits[idx] = bits;
}

// ---------------------------------------------------------------------------
// K0c: precompute biasT[h][j][i] = table[rel_idx[i*L+j]*NHEAD + h].
// grid: NHEAD*BJ blocks, BI threads.
// ---------------------------------------------------------------------------
__global__ __launch_bounds__(BI)
void bias_kernel(const int* __restrict__ rel_idx, const float* __restrict__ table)
{
    int h = blockIdx.x / BJ, j = blockIdx.x % BJ;
    int i = threadIdx.x;
    float v = 0.0f;
    if (j < LWIN && i < LWIN)
        v = __ldg(table + (size_t)__ldg(rel_idx + (size_t)i * LWIN + j) * NHEAD + h);
    g_bias[((size_t)h * BJ + j) * BI + i] = v;
}

// ---------------------------------------------------------------------------
// 64x128 output tile GEMM mainloop, K=384, 128 threads, f32x2 accumulators.
// ---------------------------------------------------------------------------
__device__ __forceinline__ void gemm_tile(const float* __restrict__ A,
                                          const float* __restrict__ B,
                                          int Nlen, int m0, int n0,
                                          u64 acc[8][4])
{
    __shared__ float As[16 * 64];
    __shared__ float Bs[16 * 128];

    const int tid = threadIdx.x;
    const int tx = tid & 15, ty = tid >> 4;

#pragma unroll
    for (int i = 0; i < 8; i++)
#pragma unroll
        for (int p = 0; p < 4; p++) acc[i][p] = 0ULL;

    for (int k0 = 0; k0 < DIMM; k0 += 16) {
#pragma unroll
        for (int u = 0; u < 2; u++) {
            int idx = tid + u * 128;
            int row = idx >> 2, c4 = idx & 3;
            float4 av = *(const float4*)(A + (size_t)(m0 + row) * DIMM + k0 + c4 * 4);
            As[(c4 * 4 + 0) * 64 + row] = av.x;
            As[(c4 * 4 + 1) * 64 + row] = av.y;
            As[(c4 * 4 + 2) * 64 + row] = av.z;
            As[(c4 * 4 + 3) * 64 + row] = av.w;
        }
#pragma unroll
        for (int u = 0; u < 4; u++) {
            int idx = tid + u * 128;
            int kr = idx >> 5, c4 = idx & 31;
            *(float4*)(Bs + kr * 128 + c4 * 4) =
                *(const float4*)(B + (size_t)(k0 + kr) * Nlen + n0 + c4 * 4);
        }
        __syncthreads();
#pragma unroll
        for (int k = 0; k < 16; k++) {
            float4 aLo = *(const float4*)(As + k * 64 + ty * 4);
            float4 aHi = *(const float4*)(As + k * 64 + 32 + ty * 4);
            F4U bLo, bHi;
            bLo.f = *(const float4*)(Bs + k * 128 + tx * 4);
            bHi.f = *(const float4*)(Bs + k * 128 + 64 + tx * 4);
            u64 b0 = bLo.u[0], b1 = bLo.u[1], b2 = bHi.u[0], b3 = bHi.u[1];
            float a[8] = {aLo.x, aLo.y, aLo.z, aLo.w, aHi.x, aHi.y, aHi.z, aHi.w};
#pragma unroll
            for (int i = 0; i < 8; i++) {
                u64 a2 = pack2(a[i], a[i]);
                fma2(acc[i][0], a2, b0);
                fma2(acc[i][1], a2, b1);
                fma2(acc[i][2], a2, b2);
                fma2(acc[i][3], a2, b3);
            }
        }
        __syncthreads();
    }
}

// ---------------------------------------------------------------------------
// K1: QKV projection + scatter. grid(9, 343), 128 threads.
// ---------------------------------------------------------------------------
__global__ __launch_bounds__(128)
void qkv_gemm_kernel(const float* __restrict__ x, const float* __restrict__ w)
{
    u64 acc[8][4];
    const int m0 = blockIdx.y * 64, n0 = blockIdx.x * 128;
    gemm_tile(x, w, 3 * DIMM, m0, n0, acc);

    const int tx = threadIdx.x & 15, ty = threadIdx.x >> 4;
    const int three = n0 / DIMM;
    float* dst = (three == 0) ? g_q : (three == 1 ? g_k : g_v);
    const float sc = (three == 0) ? QK_SCALE : 1.0f;
    const int nb = n0 - three * DIMM;

#pragma unroll
    for (int i = 0; i < 8; i++) {
        int r = m0 + ((i < 4) ? (ty * 4 + i) : (32 + ty * 4 + i - 4));
        int n = r / LWIN, l = r - n * LWIN;
#pragma unroll
        for (int p = 0; p < 4; p++) {
            float2 v = unpk2(acc[i][p]);
            int c0 = nb + ((p < 2) ? (tx * 4 + 2 * p) : (64 + tx * 4 + 2 * (p - 2)));
            int h  = c0 >> 5, ch = c0 & 31;
            dst[(size_t)((n * NHEAD + h) * LWIN + l) * HEADD + ch] = v.x * sc;
            int c1 = c0 + 1; h = c1 >> 5; ch = c1 & 31;
            dst[(size_t)((n * NHEAD + h) * LWIN + l) * HEADD + ch] = v.y * sc;
        }
    }
}

// ---------------------------------------------------------------------------
// K2: flash-style attention. grid(12, 64) = (head, window), 352 threads.
// lane = query row; Q/O/softmax state in registers; K/V broadcast from SMEM.
// ---------------------------------------------------------------------------
#define ATTN_SMEM_BYTES (BJ * HEADD * 2 * 4)   // 90112

__global__ __launch_bounds__(BJ, 1)
void attn_kernel()
{
    extern __shared__ float smem[];
    float* Ks = smem;                  // [352][32]
    float* Vs = smem + BJ * HEADD;     // [352][32]

    const int h   = blockIdx.x;
    const int win = blockIdx.y;
    const int tid = threadIdx.x;
    const int row  = tid;              // 0..351
    const int rowc = (row < LWIN) ? row : (LWIN - 1);
    const size_t base = (size_t)(win * NHEAD + h) * LWIN * HEADD;

    for (int idx = tid; idx < LWIN * HEADD; idx += BJ) {
        Ks[idx] = g_k[base + idx];
        Vs[idx] = g_v[base + idx];
    }
    for (int idx = LWIN * HEADD + tid; idx < BJ * HEADD; idx += BJ) {
        Ks[idx] = 0.0f;
        Vs[idx] = 0.0f;
    }
    __syncthreads();

    // Q row in registers (pre-scaled by QK_SCALE in K1)
    F4U q[8];
    const float4* qp = (const float4*)(g_q + base + (size_t)rowc * HEADD);
#pragma unroll
    for (int i = 0; i < 8; i++) q[i].f = qp[i];

    u64 O[16];
#pragma unroll
    for (int i = 0; i < 16; i++) O[i] = 0ULL;
    float m = -1e30f, l = 0.0f;

    const unsigned* mrow = g_maskbits + (size_t)(win * LWIN + rowc) * MWPR;
    const float*    brow = g_bias + (size_t)h * BJ * BI + rowc;

    for (int jc = 0; jc < NCHUNK; jc++) {
        const unsigned mw = __ldg(mrow + jc);
        const float*   bp = brow + (size_t)(jc * 32) * BI;

        float s[32];
#pragma unroll
        for (int jj = 0; jj < 32; jj++) {
            const F4U* kp = (const F4U*)(Ks + (jc * 32 + jj) * HEADD);
            u64 a0 = 0ULL, a1 = 0ULL;
#pragma unroll
            for (int c4 = 0; c4 < 8; c4 += 2) {
                F4U k0 = kp[c4], k1 = kp[c4 + 1];
                fma2(a0, q[c4].u[0],     k0.u[0]);
                fma2(a0, q[c4].u[1],     k0.u[1]);
                fma2(a1, q[c4 + 1].u[0], k1.u[0]);
                fma2(a1, q[c4 + 1].u[1], k1.u[1]);
            }
            float2 e0 = unpk2(a0), e1 = unpk2(a1);
            float sv = (e0.x + e1.x) + (e0.y + e1.y) + __ldg(bp + (size_t)jj * BI);
            if ((mw >> jj) & 1u) sv = -1e30f;
            s[jj] = sv;
        }

        float mc = s[0];
#pragma unroll
        for (int jj = 1; jj < 32; jj++) mc = fmaxf(mc, s[jj]);
        float mn = fmaxf(m, mc);
        float scale = __expf(m - mn);
        m = mn;
        l *= scale;
        u64 sc2 = pack2(scale, scale);
#pragma unroll
        for (int i = 0; i < 16; i++) mul2(O[i], sc2);

#pragma unroll
        for (int jj = 0; jj < 32; jj++) {
            float p = __expf(s[jj] - mn);
            l += p;
            u64 p2 = pack2(p, p);
            const F4U* vp = (const F4U*)(Vs + (jc * 32 + jj) * HEADD);
#pragma unroll
            for (int c4 = 0; c4 < 8; c4++) {
                F4U v4 = vp[c4];
                fma2(O[c4 * 2],     p2, v4.u[0]);
                fma2(O[c4 * 2 + 1], p2, v4.u[1]);
            }
        }
    }

    const float inv = 1.0f / l;
    float* op = g_ao + ((size_t)(win * LWIN) + rowc) * DIMM + h * HEADD;
#pragma unroll
    for (int i = 0; i < 8; i++) {
        float2 eA = unpk2(O[i * 2]), eB = unpk2(O[i * 2 + 1]);
        float4 o4 = make_float4(eA.x * inv, eA.y * inv, eB.x * inv, eB.y * inv);
        *(float4*)(op + i * 4) = o4;    // pad lanes rewrite row 342 with identical values
    }
}

// ---------------------------------------------------------------------------
// K3: out = g_ao @ proj_w + proj_b. grid(3, 343), 128 threads.
// ---------------------------------------------------------------------------
__global__ __launch_bounds__(128)
void proj_gemm_kernel(const float* __restrict__ w, const float* __restrict__ b,
                      float* __restrict__ out)
{
    u64 acc[8][4];
    const int m0 = blockIdx.y * 64, n0 = blockIdx.x * 128;
    gemm_tile(g_ao, w, DIMM, m0, n0, acc);

    const int tx = threadIdx.x & 15, ty = threadIdx.x >> 4;
#pragma unroll
    for (int i = 0; i < 8; i++) {
        int r = m0 + ((i < 4) ? (ty * 4 + i) : (32 + ty * 4 + i - 4));
#pragma unroll
        for (int p = 0; p < 4; p++) {
            float2 v = unpk2(acc[i][p]);
            int c0 = n0 + ((p < 2) ? (tx * 4 + 2 * p) : (64 + tx * 4 + 2 * (p - 2)));
            out[(size_t)r * DIMM + c0]     = v.x + b[c0];
            out[(size_t)r * DIMM + c0 + 1] = v.y + b[c0 + 1];
        }
    }
}

extern "C" void kernel_launch(void* const* d_in, const int* in_sizes, int n_in,
                              void* d_out, int out_size)
{
    const float* x       = (const float*)d_in[0];
    const float* qkv_w   = (const float*)d_in[1];
    const float* table   = (const float*)d_in[2];
    const float* proj_w  = (const float*)d_in[3];
    const float* proj_b  = (const float*)d_in[4];
    const void*  mask    = d_in[5];
    const int*   rel_idx = (const int*)d_in[6];
    float*       out     = (float*)d_out;

    detect_mask_kernel<<<1, 32>>>((const unsigned int*)mask);
    convert_mask_kernel<<<(NWIN * LWIN * MWPR + 255) / 256, 256>>>(mask);
    bias_kernel<<<NHEAD * BJ, BI>>>(rel_idx, table);

    qkv_gemm_kernel<<<dim3(9, 343), 128>>>(x, qkv_w);

    cudaFuncSetAttribute(attn_kernel, cudaFuncAttributeMaxDynamicSharedMemorySize,
                         ATTN_SMEM_BYTES);
    attn_kernel<<<dim3(NHEAD, NWIN), BJ, ATTN_SMEM_BYTES>>>();

    proj_gemm_kernel<<<dim3(3, 343), 128>>>(proj_w, proj_b, out);
}

// round 7
// speedup vs baseline: 1.1824x; 1.0132x over previous
#include <cuda_runtime.h>
#include <cuda_bf16.h>
#include <mma.h>

#define NWIN  64
#define NHEAD 12
#define LWIN  343
#define DIMM  384
#define HEADD 32
#define TBL   2197
#define MROWS (NWIN * LWIN)            // 21952
#define QK_SCALE 0.1767766952966369f   // 32^-0.5
#define MWPR  12
#define BJ    352
#define BI    344
#define NCHUNK 11
#define SPAD  24                       // smem row stride (bf16): 48B

typedef unsigned long long u64;
typedef __nv_bfloat16 bf16;
using namespace nvcuda;

// --- device globals: ONLY referenced inside device code, never passed from host ---
__device__ __align__(16) float g_q [NWIN * NHEAD * LWIN * HEADD];
__device__ __align__(16) float g_k [NWIN * NHEAD * LWIN * HEADD];
__device__ __align__(16) float g_v [NWIN * NHEAD * LWIN * HEADD];
__device__ __align__(16) float g_ao[MROWS * DIMM];
__device__ __align__(16) float g_bias[NHEAD * BJ * BI];
__device__ __align__(16) float g_raw[MROWS * 3 * DIMM];
__device__ int g_mask_mode;
__device__ unsigned g_maskbits[NWIN * LWIN * MWPR];

__device__ __align__(16) bf16 g_x_hi [MROWS * DIMM];
__device__ __align__(16) bf16 g_x_lo [MROWS * DIMM];
__device__ __align__(16) bf16 g_ao_hi[MROWS * DIMM];
__device__ __align__(16) bf16 g_ao_lo[MROWS * DIMM];
__device__ __align__(16) bf16 g_wq_hi[3 * DIMM * DIMM];   // qkv_w^T  [1152][384]
__device__ __align__(16) bf16 g_wq_lo[3 * DIMM * DIMM];
__device__ __align__(16) bf16 g_wp_hi[DIMM * DIMM];       // proj_w^T [384][384]
__device__ __align__(16) bf16 g_wp_lo[DIMM * DIMM];

union F4U { float4 f; u64 u[2]; };

__device__ __forceinline__ u64 pack2(float a, float b) {
    u64 r; asm("mov.b64 %0,{%1,%2};" : "=l"(r) : "f"(a), "f"(b)); return r;
}
__device__ __forceinline__ float2 unpk2(u64 v) {
    float2 r; asm("mov.b64 {%0,%1},%2;" : "=f"(r.x), "=f"(r.y) : "l"(v)); return r;
}
__device__ __forceinline__ void fma2(u64& d, u64 a, u64 b) {
    asm("fma.rn.f32x2 %0,%1,%2,%0;" : "+l"(d) : "l"(a), "l"(b));
}
__device__ __forceinline__ void mul2(u64& d, u64 s) {
    asm("mul.rn.f32x2 %0,%0,%1;" : "+l"(d) : "l"(s));
}

// ---------------------------------------------------------------------------
// mask detect / bit-pack / bias precompute (proven)
// ---------------------------------------------------------------------------
__global__ void detect_mask_kernel(const unsigned int* __restrict__ m)
{
    if (threadIdx.x == 0) {
        bool sawF32 = false, sawHigh = false;
        for (int i = 0; i < 256; i++) {
            unsigned w = m[i];
            if (w == 0x3F800000u) sawF32 = true;
            else if (w != 0u && w != 1u) sawHigh = true;
        }
        int mode = 1;
        if (sawHigh) mode = 0;
        else if (sawF32) mode = 2;
        g_mask_mode = mode;
    }
}

__global__ __launch_bounds__(256)
void convert_mask_kernel(const void* __restrict__ mraw)
{
    int idx = blockIdx.x * blockDim.x + threadIdx.x;
    if (idx >= NWIN * LWIN * MWPR) return;
    int wi  = idx % MWPR;
    int row = idx / MWPR;
    size_t base = (size_t)(row / LWIN) * LWIN * LWIN + (size_t)(row % LWIN) * LWIN;
    const int mode = g_mask_mode;
    unsigned bits = 0;
    for (int b = 0; b < 32; b++) {
        int j = wi * 32 + b;
        bool mb;
        if (j >= LWIN)          mb = true;
        else if (mode == 0)     mb = ((const unsigned char*)mraw)[base + j] != 0;
        else if (mode == 1)     mb = ((const int*)mraw)[base + j] != 0;
        else                    mb = ((const float*)mraw)[base + j] != 0.0f;
        bits |= (mb ? 1u : 0u) << b;
    }
    g_maskbits[idx] = bits;
}

__global__ __launch_bounds__(BI)
void bias_kernel(const int* __restrict__ rel_idx, const float* __restrict__ table)
{
    int h = blockIdx.x / BJ, j = blockIdx.x % BJ;
    int i = threadIdx.x;
    float v = 0.0f;
    if (j < LWIN && i < LWIN)
        v = __ldg(table + (size_t)__ldg(rel_idx + (size_t)i * LWIN + j) * NHEAD + h);
    g_bias[((size_t)h * BJ + j) * BI + i] = v;
}

// ---------------------------------------------------------------------------
// hi/lo splits. mode 0: in = x (arg) -> g_x_*;  mode 1: in = g_ao -> g_ao_*.
// ---------------------------------------------------------------------------
__global__ __launch_bounds__(256)
void split_kernel(const float* __restrict__ xin, int mode)
{
    const int n4 = MROWS * DIMM / 4;
    int i = blockIdx.x * 256 + threadIdx.x;
    if (i >= n4) return;
    const float* in = mode ? g_ao : xin;
    bf16* hi = mode ? g_ao_hi : g_x_hi;
    bf16* lo = mode ? g_ao_lo : g_x_lo;
    float4 v = ((const float4*)in)[i];
    bf16 h0 = __float2bfloat16(v.x), h1 = __float2bfloat16(v.y);
    bf16 h2 = __float2bfloat16(v.z), h3 = __float2bfloat16(v.w);
    bf16 l0 = __float2bfloat16(v.x - __bfloat162float(h0));
    bf16 l1 = __float2bfloat16(v.y - __bfloat162float(h1));
    bf16 l2 = __float2bfloat16(v.z - __bfloat162float(h2));
    bf16 l3 = __float2bfloat16(v.w - __bfloat162float(h3));
    ((__nv_bfloat162*)hi)[i * 2]     = __nv_bfloat162(h0, h1);
    ((__nv_bfloat162*)hi)[i * 2 + 1] = __nv_bfloat162(h2, h3);
    ((__nv_bfloat162*)lo)[i * 2]     = __nv_bfloat162(l0, l1);
    ((__nv_bfloat162*)lo)[i * 2 + 1] = __nv_bfloat162(l2, l3);
}

// transpose+split weights: in[K=384][N] -> (g_wq_*|g_wp_*)[N][384]. mode 0: qkv, 1: proj.
__global__ __launch_bounds__(256)
void tsplit_kernel(const float* __restrict__ in, int mode)
{
    __shared__ float tile[32][33];
    const int N = mode ? DIMM : 3 * DIMM;
    bf16* hi = mode ? g_wp_hi : g_wq_hi;
    bf16* lo = mode ? g_wp_lo : g_wq_lo;
    int n0 = blockIdx.x * 32, k0 = blockIdx.y * 32;
    int tx = threadIdx.x, ty = threadIdx.y;
#pragma unroll
    for (int i = 0; i < 32; i += 8)
        tile[ty + i][tx] = in[(size_t)(k0 + ty + i) * N + n0 + tx];
    __syncthreads();
#pragma unroll
    for (int i = 0; i < 32; i += 8) {
        float v = tile[tx][ty + i];
        bf16 h = __float2bfloat16(v);
        bf16 l = __float2bfloat16(v - __bfloat162float(h));
        size_t o = (size_t)(n0 + ty + i) * DIMM + k0 + tx;
        hi[o] = h; lo[o] = l;
    }
}

// ---------------------------------------------------------------------------
// bf16x3 WMMA GEMM -> g_raw. mode 0: x @ wq^T (N=1152); mode 1: ao @ wp^T (N=384).
// Block 64x128, 256 thr (8 warps, warp tile 32x32).
// ---------------------------------------------------------------------------
__global__ __launch_bounds__(256)
void wmma_gemm_kernel(int mode)
{
    __shared__ __align__(32) bf16 AsH[64 * SPAD],  AsL[64 * SPAD];
    __shared__ __align__(32) bf16 BsH[128 * SPAD], BsL[128 * SPAD];

    const bf16* Ahi = mode ? g_ao_hi : g_x_hi;
    const bf16* Alo = mode ? g_ao_lo : g_x_lo;
    const bf16* Bhi = mode ? g_wp_hi : g_wq_hi;
    const bf16* Blo = mode ? g_wp_lo : g_wq_lo;
    const int Nlen  = mode ? DIMM : 3 * DIMM;

    const int m0 = blockIdx.y * 64, n0 = blockIdx.x * 128;
    const int tid = threadIdx.x;
    const int w = tid >> 5;
    const int wm = w >> 2, wn = w & 3;
    const int srow = tid >> 1, shalf = tid & 1;

    wmma::fragment<wmma::accumulator, 16, 16, 16, float> c[2][2];
#pragma unroll
    for (int i = 0; i < 2; i++)
#pragma unroll
        for (int j = 0; j < 2; j++) wmma::fill_fragment(c[i][j], 0.0f);

    for (int k0 = 0; k0 < DIMM; k0 += 16) {
        if (tid < 128) {
            size_t go = (size_t)(m0 + srow) * DIMM + k0 + shalf * 8;
            *(uint4*)&AsH[srow * SPAD + shalf * 8] = *(const uint4*)&Ahi[go];
            *(uint4*)&AsL[srow * SPAD + shalf * 8] = *(const uint4*)&Alo[go];
        }
        {
            size_t go = (size_t)(n0 + srow) * DIMM + k0 + shalf * 8;
            *(uint4*)&BsH[srow * SPAD + shalf * 8] = *(const uint4*)&Bhi[go];
            *(uint4*)&BsL[srow * SPAD + shalf * 8] = *(const uint4*)&Blo[go];
        }
        __syncthreads();

        wmma::fragment<wmma::matrix_a, 16, 16, 16, bf16, wmma::row_major> aH[2], aL[2];
        wmma::fragment<wmma::matrix_b, 16, 16, 16, bf16, wmma::col_major> bH[2], bL[2];
#pragma unroll
        for (int i = 0; i < 2; i++) {
            wmma::load_matrix_sync(aH[i], &AsH[(wm * 32 + i * 16) * SPAD], SPAD);
            wmma::load_matrix_sync(aL[i], &AsL[(wm * 32 + i * 16) * SPAD], SPAD);
        }
#pragma unroll
        for (int j = 0; j < 2; j++) {
            wmma::load_matrix_sync(bH[j], &BsH[(wn * 32 + j * 16) * SPAD], SPAD);
            wmma::load_matrix_sync(bL[j], &BsL[(wn * 32 + j * 16) * SPAD], SPAD);
        }
#pragma unroll
        for (int i = 0; i < 2; i++)
#pragma unroll
            for (int j = 0; j < 2; j++) {
                wmma::mma_sync(c[i][j], aH[i], bH[j], c[i][j]);
                wmma::mma_sync(c[i][j], aH[i], bL[j], c[i][j]);
                wmma::mma_sync(c[i][j], aL[i], bH[j], c[i][j]);
            }
        __syncthreads();
    }

#pragma unroll
    for (int i = 0; i < 2; i++)
#pragma unroll
        for (int j = 0; j < 2; j++) {
            float* p = g_raw + (size_t)(m0 + wm * 32 + i * 16) * Nlen
                             + n0 + wn * 32 + j * 16;
            wmma::store_matrix_sync(p, c[i][j], Nlen, wmma::mem_row_major);
        }
}

// ---------------------------------------------------------------------------
// Scatter g_raw [M][1152] -> g_q/g_k/g_v (Q pre-scaled). float4 per thread.
// ---------------------------------------------------------------------------
__global__ __launch_bounds__(256)
void qkv_scatter_kernel()
{
    int i4 = blockIdx.x * 256 + threadIdx.x;
    const int total = MROWS * 3 * DIMM / 4;
    if (i4 >= total) return;
    int c4 = i4 % (3 * DIMM / 4);
    int m  = i4 / (3 * DIMM / 4);
    int c  = c4 * 4;
    float4 v = ((const float4*)g_raw)[i4];
    int three = c / DIMM;
    int cm = c - three * DIMM;
    int h = cm >> 5, ch = cm & 31;
    int n = m / LWIN, l = m - n * LWIN;
    float* dst = (three == 0) ? g_q : (three == 1 ? g_k : g_v);
    if (three == 0) { v.x *= QK_SCALE; v.y *= QK_SCALE; v.z *= QK_SCALE; v.w *= QK_SCALE; }
    *(float4*)&dst[(size_t)((n * NHEAD + h) * LWIN + l) * HEADD + ch] = v;
}

// ---------------------------------------------------------------------------
// Bias add: out = g_raw + proj_b. float4 per thread.
// ---------------------------------------------------------------------------
__global__ __launch_bounds__(256)
void bias_add_kernel(const float* __restrict__ b, float* __restrict__ out)
{
    int i4 = blockIdx.x * 256 + threadIdx.x;
    const int total = MROWS * DIMM / 4;
    if (i4 >= total) return;
    int c4 = i4 % (DIMM / 4);
    float4 v = ((const float4*)g_raw)[i4];
    float4 bb = ((const float4*)b)[c4];
    v.x += bb.x; v.y += bb.y; v.z += bb.z; v.w += bb.w;
    ((float4*)out)[i4] = v;
}

// ---------------------------------------------------------------------------
// K2: flash attention (proven). grid(12,64), 352 thr.
// ---------------------------------------------------------------------------
#define ATTN_SMEM_BYTES (BJ * HEADD * 2 * 4)

__global__ __launch_bounds__(BJ, 1)
void attn_kernel()
{
    extern __shared__ float smem[];
    float* Ks = smem;
    float* Vs = smem + BJ * HEADD;

    const int h   = blockIdx.x;
    const int win = blockIdx.y;
    const int tid = threadIdx.x;
    const int rowc = (tid < LWIN) ? tid : (LWIN - 1);
    const size_t base = (size_t)(win * NHEAD + h) * LWIN * HEADD;

    for (int idx = tid; idx < LWIN * HEADD; idx += BJ) {
        Ks[idx] = g_k[base + idx];
        Vs[idx] = g_v[base + idx];
    }
    for (int idx = LWIN * HEADD + tid; idx < BJ * HEADD; idx += BJ) {
        Ks[idx] = 0.0f;
        Vs[idx] = 0.0f;
    }
    __syncthreads();

    F4U q[8];
    const float4* qp = (const float4*)(g_q + base + (size_t)rowc * HEADD);
#pragma unroll
    for (int i = 0; i < 8; i++) q[i].f = qp[i];

    u64 O[16];
#pragma unroll
    for (int i = 0; i < 16; i++) O[i] = 0ULL;
    float m = -1e30f, l = 0.0f;

    const unsigned* mrow = g_maskbits + (size_t)(win * LWIN + rowc) * MWPR;
    const float*    brow = g_bias + (size_t)h * BJ * BI + rowc;

    for (int jc = 0; jc < NCHUNK; jc++) {
        const unsigned mw = __ldg(mrow + jc);
        const float*   bp = brow + (size_t)(jc * 32) * BI;

        float s[32];
#pragma unroll
        for (int jj = 0; jj < 32; jj++) {
            const F4U* kp = (const F4U*)(Ks + (jc * 32 + jj) * HEADD);
            u64 a0 = 0ULL, a1 = 0ULL;
#pragma unroll
            for (int c4 = 0; c4 < 8; c4 += 2) {
                F4U k0 = kp[c4], k1 = kp[c4 + 1];
                fma2(a0, q[c4].u[0],     k0.u[0]);
                fma2(a0, q[c4].u[1],     k0.u[1]);
                fma2(a1, q[c4 + 1].u[0], k1.u[0]);
                fma2(a1, q[c4 + 1].u[1], k1.u[1]);
            }
            float2 e0 = unpk2(a0), e1 = unpk2(a1);
            float sv = (e0.x + e1.x) + (e0.y + e1.y) + __ldg(bp + (size_t)jj * BI);
            if ((mw >> jj) & 1u) sv = -1e30f;
            s[jj] = sv;
        }

        float mc = s[0];
#pragma unroll
        for (int jj = 1; jj < 32; jj++) mc = fmaxf(mc, s[jj]);
        float mn = fmaxf(m, mc);
        float scale = __expf(m - mn);
        m = mn;
        l *= scale;
        u64 sc2 = pack2(scale, scale);
#pragma unroll
        for (int i = 0; i < 16; i++) mul2(O[i], sc2);

#pragma unroll
        for (int jj = 0; jj < 32; jj++) {
            float p = __expf(s[jj] - mn);
            l += p;
            u64 p2 = pack2(p, p);
            const F4U* vp = (const F4U*)(Vs + (jc * 32 + jj) * HEADD);
#pragma unroll
            for (int c4 = 0; c4 < 8; c4++) {
                F4U v4 = vp[c4];
                fma2(O[c4 * 2],     p2, v4.u[0]);
                fma2(O[c4 * 2 + 1], p2, v4.u[1]);
            }
        }
    }

    const float inv = 1.0f / l;
    float* op = g_ao + ((size_t)(win * LWIN) + rowc) * DIMM + h * HEADD;
#pragma unroll
    for (int i = 0; i < 8; i++) {
        float2 eA = unpk2(O[i * 2]), eB = unpk2(O[i * 2 + 1]);
        *(float4*)(op + i * 4) =
            make_float4(eA.x * inv, eA.y * inv, eB.x * inv, eB.y * inv);
    }
}

extern "C" void kernel_launch(void* const* d_in, const int* in_sizes, int n_in,
                              void* d_out, int out_size)
{
    const float* x       = (const float*)d_in[0];
    const float* qkv_w   = (const float*)d_in[1];
    const float* table   = (const float*)d_in[2];
    const float* proj_w  = (const float*)d_in[3];
    const float* proj_b  = (const float*)d_in[4];
    const void*  mask    = d_in[5];
    const int*   rel_idx = (const int*)d_in[6];
    float*       out     = (float*)d_out;

    detect_mask_kernel<<<1, 32>>>((const unsigned int*)mask);
    convert_mask_kernel<<<(NWIN * LWIN * MWPR + 255) / 256, 256>>>(mask);
    bias_kernel<<<NHEAD * BJ, BI>>>(rel_idx, table);

    const int n4 = MROWS * DIMM / 4;
    split_kernel<<<(n4 + 255) / 256, 256>>>(x, 0);
    tsplit_kernel<<<dim3(3 * DIMM / 32, DIMM / 32), dim3(32, 8)>>>(qkv_w, 0);
    tsplit_kernel<<<dim3(DIMM / 32, DIMM / 32), dim3(32, 8)>>>(proj_w, 1);

    // K1: qkv = x @ qkv_w (bf16x3 wmma) -> g_raw -> scatter
    wmma_gemm_kernel<<<dim3(9, 343), 256>>>(0);
    qkv_scatter_kernel<<<(MROWS * 3 * DIMM / 4 + 255) / 256, 256>>>();

    // K2: attention
    cudaFuncSetAttribute(attn_kernel, cudaFuncAttributeMaxDynamicSharedMemorySize,
                         ATTN_SMEM_BYTES);
    attn_kernel<<<dim3(NHEAD, NWIN), BJ, ATTN_SMEM_BYTES>>>();

    // K3: out = ao @ proj_w + b (bf16x3 wmma) -> g_raw -> bias add
    split_kernel<<<(n4 + 255) / 256, 256>>>(nullptr, 1);
    wmma_gemm_kernel<<<dim3(3, 343), 256>>>(1);
    bias_add_kernel<<<(MROWS * DIMM / 4 + 255) / 256, 256>>>(proj_b, out);
}